// round 3
// baseline (speedup 1.0000x reference)
#include <cuda_runtime.h>

#define N_NODES 100000
#define N_EDGES 3200000
#define NFEAT 128
#define HID 16
#define NC 10
#define NCP 12   // NC padded to 12 floats (48B rows, 16B-aligned)
#define NG 64

// ---------------- device scratch (allocation-free rule: __device__ globals) ----
__device__ float g_deg [N_NODES];
__device__ float g_dinv[N_NODES];
__device__ float g_h1  [N_NODES * HID];   // x @ W1
__device__ float g_agg1[N_NODES * HID];   // scatter target, then relu'd h in place
__device__ float g_h2  [N_NODES * NCP];   // h1r @ W2 (padded)
__device__ float g_agg2[N_NODES * NCP];
__device__ float g_coef[N_EDGES];
__device__ float g_pool[NG * NC];
__device__ float g_cnt [NG];

// ---------------- zero all accumulators ---------------------------------------
__global__ void k_zero() {
    int i = blockIdx.x * blockDim.x + threadIdx.x;
    int stride = gridDim.x * blockDim.x;
    for (int j = i; j < N_NODES; j += stride) g_deg[j] = 0.f;
    for (int j = i; j < N_NODES * HID; j += stride) g_agg1[j] = 0.f;
    for (int j = i; j < N_NODES * NCP; j += stride) g_agg2[j] = 0.f;
    if (i < NG * NC) g_pool[i] = 0.f;
    if (i < NG)      g_cnt[i]  = 0.f;
}

// ---------------- degree over dst ----------------------------------------------
__global__ void k_degree(const int* __restrict__ ei) {
    int e = blockIdx.x * blockDim.x + threadIdx.x;
    int stride = gridDim.x * blockDim.x;
    for (; e < N_EDGES; e += stride) {
        int d = ei[N_EDGES + e];
        atomicAdd(&g_deg[d], 1.0f);
    }
}

__global__ void k_dinv() {
    int i = blockIdx.x * blockDim.x + threadIdx.x;
    if (i < N_NODES) g_dinv[i] = rsqrtf(g_deg[i] + 1.0f);
}

// ---------------- GEMM1: h1 = x @ W1  (128 -> 16) ------------------------------
// Block handles 64 nodes. x tile staged in smem (row pitch 129 -> conflict-free),
// W1 in smem read as broadcast float4. Each thread computes 4 outputs of 1 node.
__global__ __launch_bounds__(256) void k_gemm1(const float* __restrict__ x,
                                               const float* __restrict__ W1) {
    __shared__ float sx[64 * 129];
    __shared__ float sW[NFEAT * HID];

    int tid = threadIdx.x;
    int node0 = blockIdx.x * 64;

    // load W1 (2048 floats)
    for (int j = tid; j < NFEAT * HID; j += 256) sW[j] = W1[j];

    // coalesced load of 64 x-rows into padded smem
    int nvalid = N_NODES - node0; if (nvalid > 64) nvalid = 64;
    for (int j = tid; j < 64 * NFEAT; j += 256) {
        int r = j / NFEAT, c = j % NFEAT;
        sx[r * 129 + c] = (r < nvalid) ? x[(long long)(node0 + r) * NFEAT + c] : 0.f;
    }
    __syncthreads();

    int n  = tid & 63;          // node within tile
    int og = tid >> 6;          // output group 0..3 (4 outputs each)
    if (n >= nvalid) return;

    float4 acc = make_float4(0.f, 0.f, 0.f, 0.f);
    const float4* sW4 = reinterpret_cast<const float4*>(sW);
    const float*  xr  = sx + n * 129;
#pragma unroll 8
    for (int k = 0; k < NFEAT; k++) {
        float xv = xr[k];
        float4 w = sW4[k * 4 + og];     // broadcast within warp
        acc.x += xv * w.x; acc.y += xv * w.y;
        acc.z += xv * w.z; acc.w += xv * w.w;
    }
    reinterpret_cast<float4*>(g_h1 + (node0 + n) * HID)[og] = acc;
}

// ---------------- scatter layer 1 (16-wide) ------------------------------------
__global__ void k_scatter1(const int* __restrict__ ei) {
    int e = blockIdx.x * blockDim.x + threadIdx.x;
    int stride = gridDim.x * blockDim.x;
    for (; e < N_EDGES; e += stride) {
        int s = ei[e];
        int d = ei[N_EDGES + e];
        float c = g_dinv[s] * g_dinv[d];
        g_coef[e] = c;
        const float4* hs = reinterpret_cast<const float4*>(g_h1 + (long long)s * HID);
        float* ag = g_agg1 + (long long)d * HID;
#pragma unroll
        for (int q = 0; q < 4; q++) {
            float4 v = hs[q];
            atomicAdd(ag + q * 4 + 0, v.x * c);
            atomicAdd(ag + q * 4 + 1, v.y * c);
            atomicAdd(ag + q * 4 + 2, v.z * c);
            atomicAdd(ag + q * 4 + 3, v.w * c);
        }
    }
}

// ---------------- combine1: agg1 = relu(agg1 + h1*dinv^2 + b1) ------------------
__global__ void k_combine1(const float* __restrict__ b1) {
    int i = blockIdx.x * blockDim.x + threadIdx.x;
    if (i >= N_NODES) return;
    float di = g_dinv[i];
    float sl = di * di;
    float4* ag = reinterpret_cast<float4*>(g_agg1 + (long long)i * HID);
    const float4* h = reinterpret_cast<const float4*>(g_h1 + (long long)i * HID);
    const float4* b = reinterpret_cast<const float4*>(b1);
#pragma unroll
    for (int q = 0; q < 4; q++) {
        float4 a = ag[q], hv = h[q], bv = b[q];
        a.x = fmaxf(a.x + hv.x * sl + bv.x, 0.f);
        a.y = fmaxf(a.y + hv.y * sl + bv.y, 0.f);
        a.z = fmaxf(a.z + hv.z * sl + bv.z, 0.f);
        a.w = fmaxf(a.w + hv.w * sl + bv.w, 0.f);
        ag[q] = a;
    }
}

// ---------------- GEMM2: h2 = h1r @ W2  (16 -> 10, pad to 12) -------------------
__global__ void k_gemm2(const float* __restrict__ W2) {
    __shared__ float sW[HID * NC];
    int tid = threadIdx.x;
    if (tid < HID * NC) sW[tid] = W2[tid];
    __syncthreads();
    int i = blockIdx.x * blockDim.x + tid;
    if (i >= N_NODES) return;
    float h[HID];
    const float4* hr = reinterpret_cast<const float4*>(g_agg1 + (long long)i * HID);
#pragma unroll
    for (int q = 0; q < 4; q++) {
        float4 v = hr[q];
        h[q * 4 + 0] = v.x; h[q * 4 + 1] = v.y; h[q * 4 + 2] = v.z; h[q * 4 + 3] = v.w;
    }
    float* out = g_h2 + (long long)i * NCP;
#pragma unroll
    for (int o = 0; o < NC; o++) {
        float acc = 0.f;
#pragma unroll
        for (int k = 0; k < HID; k++) acc += h[k] * sW[k * NC + o];
        out[o] = acc;
    }
    out[10] = 0.f; out[11] = 0.f;
}

// ---------------- scatter layer 2 (10-wide, padded rows) ------------------------
__global__ void k_scatter2(const int* __restrict__ ei) {
    int e = blockIdx.x * blockDim.x + threadIdx.x;
    int stride = gridDim.x * blockDim.x;
    for (; e < N_EDGES; e += stride) {
        int s = ei[e];
        int d = ei[N_EDGES + e];
        float c = g_coef[e];
        const float4* hs = reinterpret_cast<const float4*>(g_h2 + (long long)s * NCP);
        float4 v0 = hs[0], v1 = hs[1], v2 = hs[2];
        float* ag = g_agg2 + (long long)d * NCP;
        atomicAdd(ag + 0, v0.x * c); atomicAdd(ag + 1, v0.y * c);
        atomicAdd(ag + 2, v0.z * c); atomicAdd(ag + 3, v0.w * c);
        atomicAdd(ag + 4, v1.x * c); atomicAdd(ag + 5, v1.y * c);
        atomicAdd(ag + 6, v1.z * c); atomicAdd(ag + 7, v1.w * c);
        atomicAdd(ag + 8, v2.x * c); atomicAdd(ag + 9, v2.y * c);
    }
}

// ---------------- combine2 + mean-pool accumulate -------------------------------
__global__ void k_combine2(const float* __restrict__ b2,
                           const int* __restrict__ batch) {
    int i = blockIdx.x * blockDim.x + threadIdx.x;
    if (i >= N_NODES) return;
    float di = g_dinv[i];
    float sl = di * di;
    int g = batch[i];
    const float* ag = g_agg2 + (long long)i * NCP;
    const float* h  = g_h2   + (long long)i * NCP;
    float* pool = g_pool + g * NC;
#pragma unroll
    for (int o = 0; o < NC; o++) {
        float v = ag[o] + h[o] * sl + b2[o];
        atomicAdd(pool + o, v);
    }
    atomicAdd(&g_cnt[g], 1.0f);
}

// ---------------- finalize: mean + log_softmax ----------------------------------
__global__ void k_softmax(float* __restrict__ out) {
    int g = threadIdx.x;
    if (g >= NG) return;
    float cnt = fmaxf(g_cnt[g], 1.0f);
    float p[NC];
    float m = -1e30f;
#pragma unroll
    for (int o = 0; o < NC; o++) { p[o] = g_pool[g * NC + o] / cnt; m = fmaxf(m, p[o]); }
    float s = 0.f;
#pragma unroll
    for (int o = 0; o < NC; o++) s += __expf(p[o] - m);
    float l = logf(s);
#pragma unroll
    for (int o = 0; o < NC; o++) out[g * NC + o] = p[o] - m - l;
}

// ---------------- launcher -------------------------------------------------------
extern "C" void kernel_launch(void* const* d_in, const int* in_sizes, int n_in,
                              void* d_out, int out_size) {
    const float* x     = (const float*)d_in[0];
    const int*   ei    = (const int*)d_in[1];    // int32! (jax x64 disabled downcasts int64)
    const int*   batch = (const int*)d_in[2];
    const float* W1    = (const float*)d_in[3];
    const float* b1    = (const float*)d_in[4];
    const float* W2    = (const float*)d_in[5];
    const float* b2    = (const float*)d_in[6];
    float* out = (float*)d_out;

    const int TB = 256;
    const int nodeBlocks = (N_NODES + TB - 1) / TB;
    const int edgeBlocks = (N_EDGES + TB - 1) / TB;

    k_zero<<<2048, TB>>>();
    k_degree<<<edgeBlocks, TB>>>(ei);
    k_dinv<<<nodeBlocks, TB>>>();
    k_gemm1<<<(N_NODES + 63) / 64, TB>>>(x, W1);
    k_scatter1<<<edgeBlocks, TB>>>(ei);
    k_combine1<<<nodeBlocks, TB>>>(b1);
    k_gemm2<<<nodeBlocks, TB>>>(W2);
    k_scatter2<<<edgeBlocks, TB>>>(ei);
    k_combine2<<<nodeBlocks, TB>>>(b2, batch);
    k_softmax<<<1, 64>>>(out);
}

// round 4
// speedup vs baseline: 1.7594x; 1.7594x over previous
#include <cuda_runtime.h>

#define N_NODES 100000
#define N_EDGES 3200000
#define NFEAT 128
#define HID 16
#define NC 10
#define NCP 12   // NC padded to 12 floats (48B rows, 16B-aligned)
#define NG 64
#define SCAN_BLK 1024
#define N_SCAN_BLOCKS ((N_NODES + SCAN_BLK - 1) / SCAN_BLK)   // 98

// ---------------- device scratch (allocation-free rule: __device__ globals) ----
__device__ int   g_cnt_i   [N_NODES];      // in-degree (histogram over dst)
__device__ int   g_rowstart[N_NODES];      // exclusive prefix sum of g_cnt_i
__device__ int   g_cur     [N_NODES];      // fill cursors
__device__ int   g_bsum    [N_SCAN_BLOCKS];
__device__ int   g_boff    [N_SCAN_BLOCKS];
__device__ int   g_csr_src [N_EDGES];      // src node per CSR slot
__device__ float g_dinv    [N_NODES];
__device__ float g_h1      [N_NODES * HID];   // x @ W1
__device__ float g_hr      [N_NODES * HID];   // relu(conv1) output
__device__ float g_h2      [N_NODES * NCP];   // hr @ W2 (padded)
__device__ float g_pool    [NG * NC];
__device__ float g_gcnt    [NG];

// ---------------- zero the small accumulators ----------------------------------
__global__ void k_zero() {
    int i = blockIdx.x * blockDim.x + threadIdx.x;
    int stride = gridDim.x * blockDim.x;
    for (int j = i; j < N_NODES; j += stride) { g_cnt_i[j] = 0; g_cur[j] = 0; }
    if (i < NG * NC) g_pool[i] = 0.f;
    if (i < NG)      g_gcnt[i] = 0.f;
}

// ---------------- histogram over dst (int atomics are cheap) --------------------
__global__ void k_hist(const int* __restrict__ ei) {
    int e = blockIdx.x * blockDim.x + threadIdx.x;
    int stride = gridDim.x * blockDim.x;
    for (; e < N_EDGES; e += stride)
        atomicAdd(&g_cnt_i[ei[N_EDGES + e]], 1);
}

__global__ void k_dinv() {
    int i = blockIdx.x * blockDim.x + threadIdx.x;
    if (i < N_NODES) g_dinv[i] = rsqrtf((float)g_cnt_i[i] + 1.0f);
}

// ---------------- 3-phase exclusive scan of g_cnt_i -> g_rowstart ---------------
__global__ __launch_bounds__(SCAN_BLK) void k_scan_block() {
    __shared__ int sh[SCAN_BLK];
    int t = threadIdx.x;
    int i = blockIdx.x * SCAN_BLK + t;
    int v = (i < N_NODES) ? g_cnt_i[i] : 0;
    sh[t] = v;
    __syncthreads();
#pragma unroll
    for (int off = 1; off < SCAN_BLK; off <<= 1) {
        int add = (t >= off) ? sh[t - off] : 0;
        __syncthreads();
        sh[t] += add;
        __syncthreads();
    }
    if (i < N_NODES) g_rowstart[i] = sh[t] - v;          // exclusive, block-local
    if (t == SCAN_BLK - 1) g_bsum[blockIdx.x] = sh[t];   // block total
}

__global__ void k_scan_bsum() {
    if (threadIdx.x == 0) {
        int run = 0;
        for (int b = 0; b < N_SCAN_BLOCKS; b++) { g_boff[b] = run; run += g_bsum[b]; }
    }
}

__global__ void k_scan_add() {
    int i = blockIdx.x * blockDim.x + threadIdx.x;
    if (i < N_NODES) g_rowstart[i] += g_boff[i >> 10];
}

// ---------------- CSR fill -------------------------------------------------------
__global__ void k_fill(const int* __restrict__ ei) {
    int e = blockIdx.x * blockDim.x + threadIdx.x;
    int stride = gridDim.x * blockDim.x;
    for (; e < N_EDGES; e += stride) {
        int s = ei[e];
        int d = ei[N_EDGES + e];
        int pos = g_rowstart[d] + atomicAdd(&g_cur[d], 1);
        g_csr_src[pos] = s;
    }
}

// ---------------- GEMM1: h1 = x @ W1  (128 -> 16) ------------------------------
__global__ __launch_bounds__(256) void k_gemm1(const float* __restrict__ x,
                                               const float* __restrict__ W1) {
    __shared__ float sx[64 * 129];
    __shared__ float sW[NFEAT * HID];

    int tid = threadIdx.x;
    int node0 = blockIdx.x * 64;

    for (int j = tid; j < NFEAT * HID; j += 256) sW[j] = W1[j];

    int nvalid = N_NODES - node0; if (nvalid > 64) nvalid = 64;
    for (int j = tid; j < 64 * NFEAT; j += 256) {
        int r = j / NFEAT, c = j % NFEAT;
        sx[r * 129 + c] = (r < nvalid) ? x[(long long)(node0 + r) * NFEAT + c] : 0.f;
    }
    __syncthreads();

    int n  = tid & 63;
    int og = tid >> 6;
    if (n >= nvalid) return;

    float4 acc0 = make_float4(0.f, 0.f, 0.f, 0.f);
    float4 acc1 = make_float4(0.f, 0.f, 0.f, 0.f);
    const float4* sW4 = reinterpret_cast<const float4*>(sW);
    const float*  xr  = sx + n * 129;
#pragma unroll 8
    for (int k = 0; k < NFEAT; k += 2) {
        float xv0 = xr[k], xv1 = xr[k + 1];
        float4 w0 = sW4[k * 4 + og];
        float4 w1 = sW4[(k + 1) * 4 + og];
        acc0.x += xv0 * w0.x; acc0.y += xv0 * w0.y;
        acc0.z += xv0 * w0.z; acc0.w += xv0 * w0.w;
        acc1.x += xv1 * w1.x; acc1.y += xv1 * w1.y;
        acc1.z += xv1 * w1.z; acc1.w += xv1 * w1.w;
    }
    float4 acc = make_float4(acc0.x + acc1.x, acc0.y + acc1.y,
                             acc0.z + acc1.z, acc0.w + acc1.w);
    reinterpret_cast<float4*>(g_h1 + (node0 + n) * HID)[og] = acc;
}

// ---------------- gather layer 1 + combine + relu (4 threads / node) ------------
__global__ __launch_bounds__(256) void k_gather1(const float* __restrict__ b1) {
    int gt = blockIdx.x * blockDim.x + threadIdx.x;
    int node = gt >> 2;
    int part = gt & 3;
    if (node >= N_NODES) return;

    int rs  = g_rowstart[node];
    int deg = g_cnt_i[node];
    float din = g_dinv[node];

    float4 acc = make_float4(0.f, 0.f, 0.f, 0.f);
    const int* sp = g_csr_src + rs;

    int j = 0;
    for (; j + 2 <= deg; j += 2) {   // 2-way unroll for MLP
        int s0 = sp[j], s1 = sp[j + 1];
        float c0 = g_dinv[s0], c1 = g_dinv[s1];
        float4 v0 = *reinterpret_cast<const float4*>(g_h1 + s0 * HID + part * 4);
        float4 v1 = *reinterpret_cast<const float4*>(g_h1 + s1 * HID + part * 4);
        c0 *= din; c1 *= din;
        acc.x += v0.x * c0; acc.y += v0.y * c0; acc.z += v0.z * c0; acc.w += v0.w * c0;
        acc.x += v1.x * c1; acc.y += v1.y * c1; acc.z += v1.z * c1; acc.w += v1.w * c1;
    }
    if (j < deg) {
        int s0 = sp[j];
        float c0 = din * g_dinv[s0];
        float4 v0 = *reinterpret_cast<const float4*>(g_h1 + s0 * HID + part * 4);
        acc.x += v0.x * c0; acc.y += v0.y * c0; acc.z += v0.z * c0; acc.w += v0.w * c0;
    }

    float sl = din * din;
    float4 h = *reinterpret_cast<const float4*>(g_h1 + node * HID + part * 4);
    float4 b = reinterpret_cast<const float4*>(b1)[part];
    acc.x = fmaxf(acc.x + h.x * sl + b.x, 0.f);
    acc.y = fmaxf(acc.y + h.y * sl + b.y, 0.f);
    acc.z = fmaxf(acc.z + h.z * sl + b.z, 0.f);
    acc.w = fmaxf(acc.w + h.w * sl + b.w, 0.f);
    *reinterpret_cast<float4*>(g_hr + node * HID + part * 4) = acc;
}

// ---------------- GEMM2: h2 = hr @ W2  (16 -> 10, pad to 12) --------------------
__global__ void k_gemm2(const float* __restrict__ W2) {
    __shared__ float sW[HID * NC];
    int tid = threadIdx.x;
    if (tid < HID * NC) sW[tid] = W2[tid];
    __syncthreads();
    int i = blockIdx.x * blockDim.x + tid;
    if (i >= N_NODES) return;
    float h[HID];
    const float4* hr = reinterpret_cast<const float4*>(g_hr + i * HID);
#pragma unroll
    for (int q = 0; q < 4; q++) {
        float4 v = hr[q];
        h[q * 4 + 0] = v.x; h[q * 4 + 1] = v.y; h[q * 4 + 2] = v.z; h[q * 4 + 3] = v.w;
    }
    float* out = g_h2 + i * NCP;
#pragma unroll
    for (int o = 0; o < NC; o++) {
        float acc = 0.f;
#pragma unroll
        for (int k = 0; k < HID; k++) acc += h[k] * sW[k * NC + o];
        out[o] = acc;
    }
    out[10] = 0.f; out[11] = 0.f;
}

// ---------------- gather layer 2 + combine + mean-pool (thread / node) ----------
__global__ __launch_bounds__(256) void k_gather2(const float* __restrict__ b2,
                                                 const int* __restrict__ batch) {
    int i = blockIdx.x * blockDim.x + threadIdx.x;
    if (i >= N_NODES) return;

    int rs  = g_rowstart[i];
    int deg = g_cnt_i[i];
    float din = g_dinv[i];

    float acc[NC];
#pragma unroll
    for (int o = 0; o < NC; o++) acc[o] = 0.f;

    const int* sp = g_csr_src + rs;
    for (int j = 0; j < deg; j++) {
        int s = sp[j];
        float c = din * g_dinv[s];
        const float4* hv = reinterpret_cast<const float4*>(g_h2 + s * NCP);
        float4 v0 = hv[0], v1 = hv[1];
        float2 v2 = *reinterpret_cast<const float2*>(g_h2 + s * NCP + 8);
        acc[0] += v0.x * c; acc[1] += v0.y * c; acc[2] += v0.z * c; acc[3] += v0.w * c;
        acc[4] += v1.x * c; acc[5] += v1.y * c; acc[6] += v1.z * c; acc[7] += v1.w * c;
        acc[8] += v2.x * c; acc[9] += v2.y * c;
    }

    float sl = din * din;
    int g = batch[i];
    const float* h = g_h2 + i * NCP;
    float* pool = g_pool + g * NC;
#pragma unroll
    for (int o = 0; o < NC; o++)
        atomicAdd(pool + o, acc[o] + h[o] * sl + b2[o]);
    atomicAdd(&g_gcnt[g], 1.0f);
}

// ---------------- finalize: mean + log_softmax ----------------------------------
__global__ void k_softmax(float* __restrict__ out) {
    int g = threadIdx.x;
    if (g >= NG) return;
    float cnt = fmaxf(g_gcnt[g], 1.0f);
    float p[NC];
    float m = -1e30f;
#pragma unroll
    for (int o = 0; o < NC; o++) { p[o] = g_pool[g * NC + o] / cnt; m = fmaxf(m, p[o]); }
    float s = 0.f;
#pragma unroll
    for (int o = 0; o < NC; o++) s += __expf(p[o] - m);
    float l = logf(s);
#pragma unroll
    for (int o = 0; o < NC; o++) out[g * NC + o] = p[o] - m - l;
}

// ---------------- launcher -------------------------------------------------------
extern "C" void kernel_launch(void* const* d_in, const int* in_sizes, int n_in,
                              void* d_out, int out_size) {
    const float* x     = (const float*)d_in[0];
    const int*   ei    = (const int*)d_in[1];    // int32 (jax default int)
    const int*   batch = (const int*)d_in[2];
    const float* W1    = (const float*)d_in[3];
    const float* b1    = (const float*)d_in[4];
    const float* W2    = (const float*)d_in[5];
    const float* b2    = (const float*)d_in[6];
    float* out = (float*)d_out;

    const int TB = 256;
    const int nodeBlocks  = (N_NODES + TB - 1) / TB;
    const int edgeBlocks  = (N_EDGES + TB - 1) / TB;
    const int node4Blocks = (4 * N_NODES + TB - 1) / TB;

    k_zero<<<512, TB>>>();
    k_hist<<<edgeBlocks, TB>>>(ei);
    k_dinv<<<nodeBlocks, TB>>>();
    k_scan_block<<<N_SCAN_BLOCKS, SCAN_BLK>>>();
    k_scan_bsum<<<1, 32>>>();
    k_scan_add<<<nodeBlocks, TB>>>();
    k_fill<<<edgeBlocks, TB>>>(ei);
    k_gemm1<<<(N_NODES + 63) / 64, TB>>>(x, W1);
    k_gather1<<<node4Blocks, TB>>>(b1);
    k_gemm2<<<nodeBlocks, TB>>>(W2);
    k_gather2<<<nodeBlocks, TB>>>(b2, batch);
    k_softmax<<<1, 64>>>(out);
}

// round 5
// speedup vs baseline: 2.2410x; 1.2737x over previous
#include <cuda_runtime.h>

#define N_NODES 100000
#define N_EDGES 3200000
#define NFEAT 128
#define HID 16
#define NC 10
#define NCP2 16   // h2 rows padded to 16 floats (64B, 4x float4)
#define NG 64
#define SCAN_BLK 1024
#define N_SCAN_BLOCKS ((N_NODES + SCAN_BLK - 1) / SCAN_BLK)   // 98

#define GEMM1_BLOCKS ((N_NODES + 63) / 64)          // 1563
#define PRE1_QUADS   (GEMM1_BLOCKS / 3)             // 521 (1563 = 3*521)
#define PRE1_BLOCKS  (PRE1_QUADS * 4)               // 2084: 3 gemm + 1 hist per quad

// ---------------- device scratch --------------------------------------------------
__device__ int   g_cnt_i   [N_NODES];      // in-degree histogram over dst
__device__ int   g_rowstart[N_NODES];      // exclusive prefix sum
__device__ int   g_cur     [N_NODES];      // fill cursors (preloaded = rowstart)
__device__ int   g_bsum    [N_SCAN_BLOCKS];
__device__ int   g_boff    [N_SCAN_BLOCKS];
__device__ int2  g_csr     [N_EDGES];      // {src, __float_as_int(dinv[src])}
__device__ float g_dinv    [N_NODES];
__device__ float g_h1      [N_NODES * HID];    // x @ W1
__device__ float g_h2      [N_NODES * NCP2];   // relu(conv1) @ W2, padded
__device__ float g_pool    [NG * NC];
__device__ float g_gcnt    [NG];

// ---------------- zero -------------------------------------------------------------
__global__ void k_zero() {
    int i = blockIdx.x * blockDim.x + threadIdx.x;
    int stride = gridDim.x * blockDim.x;
    for (int j = i; j < N_NODES; j += stride) g_cnt_i[j] = 0;
    if (i < NG * NC) g_pool[i] = 0.f;
    if (i < NG)      g_gcnt[i] = 0.f;
}

// ---------------- fused: GEMM1 (3/4 of blocks) + dst-histogram (1/4) ---------------
__global__ __launch_bounds__(256) void k_pre1(const float* __restrict__ x,
                                              const float* __restrict__ W1,
                                              const int* __restrict__ ei) {
    __shared__ float sx[64 * 129];
    __shared__ float sW[NFEAT * HID];

    int b = blockIdx.x;
    int tid = threadIdx.x;

    if ((b & 3) == 3) {
        // ---- histogram role: grid-stride over dst half as int4 ----
        const int4* dst4 = reinterpret_cast<const int4*>(ei + N_EDGES);
        int n4 = N_EDGES / 4;
        int i = (b >> 2) * 256 + tid;
        int stride = PRE1_QUADS * 256;
        for (; i < n4; i += stride) {
            int4 d = dst4[i];
            atomicAdd(&g_cnt_i[d.x], 1);
            atomicAdd(&g_cnt_i[d.y], 1);
            atomicAdd(&g_cnt_i[d.z], 1);
            atomicAdd(&g_cnt_i[d.w], 1);
        }
        return;
    }

    // ---- gemm1 role ----
    int gb = (b >> 2) * 3 + (b & 3);      // 0..GEMM1_BLOCKS-1
    int node0 = gb * 64;

    for (int j = tid; j < NFEAT * HID; j += 256) sW[j] = W1[j];

    int nvalid = N_NODES - node0; if (nvalid > 64) nvalid = 64;
    for (int j = tid; j < 64 * NFEAT; j += 256) {
        int r = j / NFEAT, c = j % NFEAT;
        sx[r * 129 + c] = (r < nvalid) ? x[(long long)(node0 + r) * NFEAT + c] : 0.f;
    }
    __syncthreads();

    int n  = tid & 63;
    int og = tid >> 6;
    if (n >= nvalid) return;

    float4 acc0 = make_float4(0.f, 0.f, 0.f, 0.f);
    float4 acc1 = make_float4(0.f, 0.f, 0.f, 0.f);
    const float4* sW4 = reinterpret_cast<const float4*>(sW);
    const float*  xr  = sx + n * 129;
#pragma unroll 8
    for (int k = 0; k < NFEAT; k += 2) {
        float xv0 = xr[k], xv1 = xr[k + 1];
        float4 w0 = sW4[k * 4 + og];
        float4 w1 = sW4[(k + 1) * 4 + og];
        acc0.x += xv0 * w0.x; acc0.y += xv0 * w0.y;
        acc0.z += xv0 * w0.z; acc0.w += xv0 * w0.w;
        acc1.x += xv1 * w1.x; acc1.y += xv1 * w1.y;
        acc1.z += xv1 * w1.z; acc1.w += xv1 * w1.w;
    }
    float4 acc = make_float4(acc0.x + acc1.x, acc0.y + acc1.y,
                             acc0.z + acc1.z, acc0.w + acc1.w);
    reinterpret_cast<float4*>(g_h1 + (node0 + n) * HID)[og] = acc;
}

// ---------------- scan phase 1 (+ dinv) --------------------------------------------
__global__ __launch_bounds__(SCAN_BLK) void k_scan_block() {
    __shared__ int sh[SCAN_BLK];
    int t = threadIdx.x;
    int i = blockIdx.x * SCAN_BLK + t;
    int v = (i < N_NODES) ? g_cnt_i[i] : 0;
    if (i < N_NODES) g_dinv[i] = rsqrtf((float)v + 1.0f);
    sh[t] = v;
    __syncthreads();
#pragma unroll
    for (int off = 1; off < SCAN_BLK; off <<= 1) {
        int add = (t >= off) ? sh[t - off] : 0;
        __syncthreads();
        sh[t] += add;
        __syncthreads();
    }
    if (i < N_NODES) g_rowstart[i] = sh[t] - v;          // block-local exclusive
    if (t == SCAN_BLK - 1) g_bsum[blockIdx.x] = sh[t];
}

// ---------------- scan phase 2: 98-wide block scan ----------------------------------
__global__ __launch_bounds__(128) void k_scan_bsum() {
    __shared__ int sh[128];
    int t = threadIdx.x;
    int v = (t < N_SCAN_BLOCKS) ? g_bsum[t] : 0;
    sh[t] = v;
    __syncthreads();
#pragma unroll
    for (int off = 1; off < 128; off <<= 1) {
        int add = (t >= off) ? sh[t - off] : 0;
        __syncthreads();
        sh[t] += add;
        __syncthreads();
    }
    if (t < N_SCAN_BLOCKS) g_boff[t] = sh[t] - v;        // exclusive
}

// ---------------- scan phase 3 (+ cursor init) ---------------------------------------
__global__ void k_scan_add() {
    int i = blockIdx.x * blockDim.x + threadIdx.x;
    if (i < N_NODES) {
        int rs = g_rowstart[i] + g_boff[i >> 10];
        g_rowstart[i] = rs;
        g_cur[i] = rs;
    }
}

// ---------------- CSR fill: {src, dinv[src]} ------------------------------------------
__global__ void k_fill(const int* __restrict__ ei) {
    int e = blockIdx.x * blockDim.x + threadIdx.x;
    if (e >= N_EDGES) return;
    int s = ei[e];
    int d = ei[N_EDGES + e];
    float ds = g_dinv[s];
    int pos = atomicAdd(&g_cur[d], 1);
    g_csr[pos] = make_int2(s, __float_as_int(ds));
}

// ---------------- gather1 + combine1 + relu + GEMM2 (4 threads / node) ----------------
__global__ __launch_bounds__(256) void k_gather1(const float* __restrict__ b1,
                                                 const float* __restrict__ W2) {
    __shared__ float sW2[HID * NC];
    int tid = threadIdx.x;
    if (tid < HID * NC) sW2[tid] = W2[tid];
    __syncthreads();

    int gt = blockIdx.x * blockDim.x + tid;
    int node = gt >> 2;
    bool valid = node < N_NODES;
    if (!valid) node = N_NODES - 1;          // clamp; keep lanes alive for shfl
    int part = tid & 3;

    int rs  = g_rowstart[node];
    int deg = g_cnt_i[node];
    float din = g_dinv[node];

    const int2* sp = g_csr + rs;
    float4 acc = make_float4(0.f, 0.f, 0.f, 0.f);

    int j = 0;
    for (; j + 4 <= deg; j += 4) {
        int2 p0 = sp[j], p1 = sp[j + 1], p2 = sp[j + 2], p3 = sp[j + 3];
        float4 v0 = *reinterpret_cast<const float4*>(g_h1 + p0.x * HID + part * 4);
        float4 v1 = *reinterpret_cast<const float4*>(g_h1 + p1.x * HID + part * 4);
        float4 v2 = *reinterpret_cast<const float4*>(g_h1 + p2.x * HID + part * 4);
        float4 v3 = *reinterpret_cast<const float4*>(g_h1 + p3.x * HID + part * 4);
        float c0 = din * __int_as_float(p0.y);
        float c1 = din * __int_as_float(p1.y);
        float c2 = din * __int_as_float(p2.y);
        float c3 = din * __int_as_float(p3.y);
        acc.x += v0.x * c0; acc.y += v0.y * c0; acc.z += v0.z * c0; acc.w += v0.w * c0;
        acc.x += v1.x * c1; acc.y += v1.y * c1; acc.z += v1.z * c1; acc.w += v1.w * c1;
        acc.x += v2.x * c2; acc.y += v2.y * c2; acc.z += v2.z * c2; acc.w += v2.w * c2;
        acc.x += v3.x * c3; acc.y += v3.y * c3; acc.z += v3.z * c3; acc.w += v3.w * c3;
    }
    for (; j < deg; j++) {
        int2 p = sp[j];
        float c = din * __int_as_float(p.y);
        float4 v = *reinterpret_cast<const float4*>(g_h1 + p.x * HID + part * 4);
        acc.x += v.x * c; acc.y += v.y * c; acc.z += v.z * c; acc.w += v.w * c;
    }

    // combine + relu -> this thread's 4-wide slice of hr
    float sl = din * din;
    float4 h = *reinterpret_cast<const float4*>(g_h1 + node * HID + part * 4);
    float4 b = reinterpret_cast<const float4*>(b1)[part];
    float4 a;
    a.x = fmaxf(acc.x + h.x * sl + b.x, 0.f);
    a.y = fmaxf(acc.y + h.y * sl + b.y, 0.f);
    a.z = fmaxf(acc.z + h.z * sl + b.z, 0.f);
    a.w = fmaxf(acc.w + h.w * sl + b.w, 0.f);

    // exchange the 16-wide hr row among the 4 lanes of this node
    float hr[HID];
    unsigned lanebase = (unsigned)(tid & 31) & ~3u;
#pragma unroll
    for (int q = 0; q < 4; q++) {
        hr[q * 4 + 0] = __shfl_sync(0xffffffffu, a.x, lanebase + q);
        hr[q * 4 + 1] = __shfl_sync(0xffffffffu, a.y, lanebase + q);
        hr[q * 4 + 2] = __shfl_sync(0xffffffffu, a.z, lanebase + q);
        hr[q * 4 + 3] = __shfl_sync(0xffffffffu, a.w, lanebase + q);
    }

    // gemm2: this thread computes output cols [part*4, part*4+4) (cols >= NC are 0-pad)
    float4 o = make_float4(0.f, 0.f, 0.f, 0.f);
    float* op = &o.x;
#pragma unroll
    for (int c = 0; c < 4; c++) {
        int col = part * 4 + c;
        if (col < NC) {
            float s = 0.f;
#pragma unroll
            for (int k = 0; k < HID; k++) s += hr[k] * sW2[k * NC + col];
            op[c] = s;
        }
    }
    if (valid)
        *reinterpret_cast<float4*>(g_h2 + node * NCP2 + part * 4) = o;
}

// ---------------- gather2 + combine2 + mean-pool (4 threads / node) --------------------
__global__ __launch_bounds__(256) void k_gather2(const float* __restrict__ b2,
                                                 const int* __restrict__ batch) {
    int gt = blockIdx.x * blockDim.x + threadIdx.x;
    int node = gt >> 2;
    if (node >= N_NODES) return;
    int part = gt & 3;

    int rs  = g_rowstart[node];
    int deg = g_cnt_i[node];
    float din = g_dinv[node];

    const int2* sp = g_csr + rs;
    float4 acc = make_float4(0.f, 0.f, 0.f, 0.f);

    int j = 0;
    for (; j + 4 <= deg; j += 4) {
        int2 p0 = sp[j], p1 = sp[j + 1], p2 = sp[j + 2], p3 = sp[j + 3];
        float4 v0 = *reinterpret_cast<const float4*>(g_h2 + p0.x * NCP2 + part * 4);
        float4 v1 = *reinterpret_cast<const float4*>(g_h2 + p1.x * NCP2 + part * 4);
        float4 v2 = *reinterpret_cast<const float4*>(g_h2 + p2.x * NCP2 + part * 4);
        float4 v3 = *reinterpret_cast<const float4*>(g_h2 + p3.x * NCP2 + part * 4);
        float c0 = din * __int_as_float(p0.y);
        float c1 = din * __int_as_float(p1.y);
        float c2 = din * __int_as_float(p2.y);
        float c3 = din * __int_as_float(p3.y);
        acc.x += v0.x * c0; acc.y += v0.y * c0; acc.z += v0.z * c0; acc.w += v0.w * c0;
        acc.x += v1.x * c1; acc.y += v1.y * c1; acc.z += v1.z * c1; acc.w += v1.w * c1;
        acc.x += v2.x * c2; acc.y += v2.y * c2; acc.z += v2.z * c2; acc.w += v2.w * c2;
        acc.x += v3.x * c3; acc.y += v3.y * c3; acc.z += v3.z * c3; acc.w += v3.w * c3;
    }
    for (; j < deg; j++) {
        int2 p = sp[j];
        float c = din * __int_as_float(p.y);
        float4 v = *reinterpret_cast<const float4*>(g_h2 + p.x * NCP2 + part * 4);
        acc.x += v.x * c; acc.y += v.y * c; acc.z += v.z * c; acc.w += v.w * c;
    }

    float sl = din * din;
    float4 h = *reinterpret_cast<const float4*>(g_h2 + node * NCP2 + part * 4);
    int g = batch[node];
    float* pool = g_pool + g * NC;

    float res[4] = { acc.x + h.x * sl, acc.y + h.y * sl,
                     acc.z + h.z * sl, acc.w + h.w * sl };
#pragma unroll
    for (int c = 0; c < 4; c++) {
        int col = part * 4 + c;
        if (col < NC) atomicAdd(pool + col, res[c] + b2[col]);
    }
    if (part == 0) atomicAdd(&g_gcnt[g], 1.0f);
}

// ---------------- finalize: mean + log_softmax ------------------------------------------
__global__ void k_softmax(float* __restrict__ out) {
    int g = threadIdx.x;
    if (g >= NG) return;
    float cnt = fmaxf(g_gcnt[g], 1.0f);
    float p[NC];
    float m = -1e30f;
#pragma unroll
    for (int o = 0; o < NC; o++) { p[o] = g_pool[g * NC + o] / cnt; m = fmaxf(m, p[o]); }
    float s = 0.f;
#pragma unroll
    for (int o = 0; o < NC; o++) s += __expf(p[o] - m);
    float l = logf(s);
#pragma unroll
    for (int o = 0; o < NC; o++) out[g * NC + o] = p[o] - m - l;
}

// ---------------- launcher ----------------------------------------------------------------
extern "C" void kernel_launch(void* const* d_in, const int* in_sizes, int n_in,
                              void* d_out, int out_size) {
    const float* x     = (const float*)d_in[0];
    const int*   ei    = (const int*)d_in[1];    // int32 (jax default int)
    const int*   batch = (const int*)d_in[2];
    const float* W1    = (const float*)d_in[3];
    const float* b1    = (const float*)d_in[4];
    const float* W2    = (const float*)d_in[5];
    const float* b2    = (const float*)d_in[6];
    float* out = (float*)d_out;

    const int TB = 256;
    const int nodeBlocks  = (N_NODES + TB - 1) / TB;          // 391
    const int edgeBlocks  = (N_EDGES + TB - 1) / TB;          // 12500
    const int node4Blocks = (4 * N_NODES + TB - 1) / TB;      // 1563

    k_zero<<<128, TB>>>();
    k_pre1<<<PRE1_BLOCKS, TB>>>(x, W1, ei);
    k_scan_block<<<N_SCAN_BLOCKS, SCAN_BLK>>>();
    k_scan_bsum<<<1, 128>>>();
    k_scan_add<<<nodeBlocks, TB>>>();
    k_fill<<<edgeBlocks, TB>>>(ei);
    k_gather1<<<node4Blocks, TB>>>(b1, W2);
    k_gather2<<<node4Blocks, TB>>>(b2, batch);
    k_softmax<<<1, 64>>>(out);
}